// round 13
// baseline (speedup 1.0000x reference)
#include <cuda_runtime.h>
#include <cstdint>
#include <mma.h>

using namespace nvcuda;

#define BB 2
#define SS 2048
#define DD 1024
#define HH 16
#define HD 64
#define NROWS (BB*SS)

__device__ float g_q[NROWS*DD];        // [B,H,S,HD]  (tf32-rounded)
__device__ float g_k[NROWS*DD];        // [B,H,S,HD]  (tf32-rounded)
__device__ float g_v[NROWS*DD];        // [B,H,S,HD]  (tf32-rounded)
__device__ float g_ctx[NROWS*DD];      // [B,S,D]     (tf32-rounded)
__device__ float g_xt[NROWS*DD];       // tf32(x)
__device__ float g_wt4[4*DD*DD];       // tf32(Wq,Wk,Wv,Wo)

__device__ __forceinline__ uint32_t smem_u32(const void* p) {
    uint32_t a;
    asm("{ .reg .u64 t; cvta.to.shared.u64 t, %1; cvt.u32.u64 %0, t; }" : "=r"(a) : "l"(p));
    return a;
}
__device__ __forceinline__ float rtf(float x) {
    uint32_t u;
    asm("cvt.rna.tf32.f32 %0, %1;" : "=r"(u) : "f"(x));
    return __uint_as_float(u);
}
__device__ __forceinline__ float4 rtf4(float4 v) {
    v.x = rtf(v.x); v.y = rtf(v.y); v.z = rtf(v.z); v.w = rtf(v.w);
    return v;
}
#define CP_ASYNC16(s, g) \
    asm volatile("cp.async.cg.shared.global [%0], [%1], 16;" :: "r"(s), "l"(g))
#define CP_COMMIT() asm volatile("cp.async.commit_group;")
#define CP_WAIT0()  asm volatile("cp.async.wait_group 0;" ::: "memory")

// ---------------------------------------------------------------------------
// Pre-convert x and all W to tf32-rounded copies
// ---------------------------------------------------------------------------
__global__ __launch_bounds__(256) void conv_tf32(
    const float* __restrict__ x,
    const float* __restrict__ Wq, const float* __restrict__ Wk,
    const float* __restrict__ Wv, const float* __restrict__ Wo)
{
    const int z = blockIdx.z;
    const float* src; float* dst; int n4;
    if (z == 0)      { src = x;  dst = g_xt;              n4 = NROWS * DD / 4; }
    else if (z == 1) { src = Wq; dst = g_wt4;             n4 = DD * DD / 4; }
    else if (z == 2) { src = Wk; dst = g_wt4 + DD * DD;   n4 = DD * DD / 4; }
    else if (z == 3) { src = Wv; dst = g_wt4 + 2*DD*DD;   n4 = DD * DD / 4; }
    else             { src = Wo; dst = g_wt4 + 3*DD*DD;   n4 = DD * DD / 4; }
    const int stride = gridDim.x * blockDim.x;
    for (int i = blockIdx.x * blockDim.x + threadIdx.x; i < n4; i += stride)
        *(float4*)&dst[i * 4] = rtf4(*(const float4*)&src[i * 4]);
}

// ---------------------------------------------------------------------------
// tf32 WMMA GEMM (unchanged from R12)
// ---------------------------------------------------------------------------
#define AS_STRIDE 36
#define BS_STRIDE 136
#define AS_FLOATS (128 * AS_STRIDE)
#define BS_FLOATS (32 * BS_STRIDE)
#define SMEM_BYTES  (2 * (AS_FLOATS + BS_FLOATS) * 4)   // 71680
#define ST_STRIDE 132

template<bool SCATTER>
__global__ __launch_bounds__(256, 2) void gemm_wmma(
    const float* __restrict__ bi0, const float* __restrict__ bi1, const float* __restrict__ bi2,
    float* __restrict__ Yout)
{
    extern __shared__ float smem[];
    float* sA = smem;
    float* sB = smem + 2 * AS_FLOATS;

    const int tid  = threadIdx.x;
    const int wid  = tid >> 5;
    const int wm   = wid & 1;
    const int wn   = wid >> 1;

    const float* __restrict__ A = SCATTER ? g_xt : g_ctx;
    const float* __restrict__ W;
    const float* __restrict__ bias;
    float* __restrict__ outp;
    if (SCATTER) {
        const int z = blockIdx.z;
        W    = g_wt4 + (size_t)z * DD * DD;
        bias = (z == 0) ? bi0 : (z == 1) ? bi1 : bi2;
        outp = (z == 0) ? g_q : (z == 1) ? g_k : g_v;
    } else {
        W = g_wt4 + (size_t)3 * DD * DD; bias = bi0; outp = Yout;
    }

    const int rowBase = blockIdx.y * 128;
    const int colBase = blockIdx.x * 128;

    wmma::fragment<wmma::accumulator, 16, 16, 8, float> acc[4][2];
#pragma unroll
    for (int mt = 0; mt < 4; mt++)
#pragma unroll
        for (int nt = 0; nt < 2; nt++)
            wmma::fill_fragment(acc[mt][nt], 0.f);

    const uint32_t sAu = smem_u32(sA);
    const uint32_t sBu = smem_u32(sB);

    auto load_tile = [&](int it, int buf) {
        const int k0 = it * 32;
        uint32_t aBase = sAu + buf * AS_FLOATS * 4;
        uint32_t bBase = sBu + buf * BS_FLOATS * 4;
#pragma unroll
        for (int i = 0; i < 4; i++) {
            int ch = tid + i * 256;
            int m = ch >> 3, kq = ch & 7;
            CP_ASYNC16(aBase + (m * AS_STRIDE + kq * 4) * 4,
                       &A[(size_t)(rowBase + m) * DD + k0 + kq * 4]);
        }
#pragma unroll
        for (int i = 0; i < 4; i++) {
            int ch = tid + i * 256;
            int kk = ch >> 5, nq = ch & 31;
            CP_ASYNC16(bBase + (kk * BS_STRIDE + nq * 4) * 4,
                       &W[(size_t)(k0 + kk) * DD + colBase + nq * 4]);
        }
        CP_COMMIT();
    };

    load_tile(0, 0);
    CP_WAIT0();
    __syncthreads();

    const int NT = DD / 32;
    for (int it = 0; it < NT; it++) {
        const int buf = it & 1;
        if (it + 1 < NT) load_tile(it + 1, buf ^ 1);

        const float* As = sA + buf * AS_FLOATS;
        const float* Bs = sB + buf * BS_FLOATS;

#pragma unroll
        for (int ks = 0; ks < 4; ks++) {
            const int k = ks * 8;
            wmma::fragment<wmma::matrix_a, 16, 16, 8, wmma::precision::tf32, wmma::row_major> af[4];
            wmma::fragment<wmma::matrix_b, 16, 16, 8, wmma::precision::tf32, wmma::row_major> bf[2];
#pragma unroll
            for (int mt = 0; mt < 4; mt++)
                wmma::load_matrix_sync(af[mt], As + (wm * 64 + mt * 16) * AS_STRIDE + k, AS_STRIDE);
#pragma unroll
            for (int nt = 0; nt < 2; nt++)
                wmma::load_matrix_sync(bf[nt], Bs + k * BS_STRIDE + wn * 32 + nt * 16, BS_STRIDE);
#pragma unroll
            for (int mt = 0; mt < 4; mt++)
#pragma unroll
                for (int nt = 0; nt < 2; nt++)
                    wmma::mma_sync(acc[mt][nt], af[mt], bf[nt], acc[mt][nt]);
        }

        if (it + 1 < NT) CP_WAIT0();
        __syncthreads();
    }

    float* stage = smem;
#pragma unroll
    for (int mt = 0; mt < 4; mt++)
#pragma unroll
        for (int nt = 0; nt < 2; nt++)
            wmma::store_matrix_sync(stage + (wm * 64 + mt * 16) * ST_STRIDE + wn * 32 + nt * 16,
                                    acc[mt][nt], ST_STRIDE, wmma::mem_row_major);
    __syncthreads();

    const int rr   = tid >> 1;
    const int half = tid & 1;
    const int row  = rowBase + rr;
    const int bb   = row >> 11;
    const int s    = row & (SS - 1);
    if (SCATTER) {
        const int colG = colBase + half * 64;
        const int h = colG >> 6;
        float* dst = &outp[(((size_t)(bb * HH + h)) * SS + s) * HD];
#pragma unroll
        for (int j = 0; j < 16; j++) {
            const int cl = half * 64 + j * 4;
            float4 v  = *(const float4*)&stage[rr * ST_STRIDE + cl];
            float4 bv = *(const float4*)&bias[colBase + cl];
            v.x += bv.x; v.y += bv.y; v.z += bv.z; v.w += bv.w;
            *(float4*)&dst[j * 4] = rtf4(v);
        }
    } else {
        float* dst = &outp[(size_t)row * DD + colBase];
#pragma unroll
        for (int j = 0; j < 16; j++) {
            const int cl = half * 64 + j * 4;
            float4 v  = *(const float4*)&stage[rr * ST_STRIDE + cl];
            float4 bv = *(const float4*)&bias[colBase + cl];
            v.x += bv.x; v.y += bv.y; v.z += bv.z; v.w += bv.w;
            *(float4*)&dst[cl] = v;
        }
    }
}

// ---------------------------------------------------------------------------
// Tensor-core causal flash attention v4 — warp-private rows.
// CTA = (qt, bh): 128 q rows, 256 threads / 8 warps; warp w owns rows w*16..+15
// exclusively through S-mma, softmax, rescale, PV-mma: NO CTA sync between
// phases, only 1 __syncthreads per k-tile (cp.async buffer rotation).
// ---------------------------------------------------------------------------
#define ATS 72
#define QROWS 128
#define QTILE_F (QROWS * ATS)            // 9216
#define KTILE_F (64 * ATS)               // 4608
// Qs + Os + SP (128 rows) + K0,K1,V0,V1 (64 rows) + m/l
#define ATT_SMEM_BYTES ((3 * QTILE_F + 4 * KTILE_F + 256) * 4)   // 185344

__global__ __launch_bounds__(256) void attn_wmma()
{
    extern __shared__ float sm[];
    float* Qs = sm;
    float* Os = Qs + QTILE_F;
    float* SP = Os + QTILE_F;
    float* Kd[2] = { SP + QTILE_F,               SP + QTILE_F + KTILE_F };
    float* Vd[2] = { SP + QTILE_F + 2 * KTILE_F, SP + QTILE_F + 3 * KTILE_F };
    float* mrow = SP + QTILE_F + 4 * KTILE_F;   // 128
    float* lrow = mrow + QROWS;                  // 128

    const int qt  = (int)gridDim.x - 1 - (int)blockIdx.x;   // heavy CTAs first
    const int bh  = blockIdx.y;
    const int tid = threadIdx.x;
    const int wid = tid >> 5;            // warp owns rows wid*16..+15
    const int lane = tid & 31;

    const uint32_t ku[2] = { smem_u32(Kd[0]), smem_u32(Kd[1]) };
    const uint32_t vu[2] = { smem_u32(Vd[0]), smem_u32(Vd[1]) };

    const float* kbase0 = &g_k[((size_t)bh * SS) * HD];
    const float* vbase0 = &g_v[((size_t)bh * SS) * HD];

    auto issue_tile = [&](int kt, int buf) {
        const float* kb = kbase0 + (size_t)kt * 64 * HD;
        const float* vb = vbase0 + (size_t)kt * 64 * HD;
#pragma unroll
        for (int i = 0; i < 4; i++) {
            int ch = tid + i * 256;
            int r = ch >> 4, c4 = (ch & 15) * 4;
            CP_ASYNC16(ku[buf] + (r * ATS + c4) * 4, kb + r * HD + c4);
        }
#pragma unroll
        for (int i = 0; i < 4; i++) {
            int ch = tid + i * 256;
            int r = ch >> 4, c4 = (ch & 15) * 4;
            CP_ASYNC16(vu[buf] + (r * ATS + c4) * 4, vb + r * HD + c4);
        }
        CP_COMMIT();
    };

    // Prologue
    issue_tile(0, 0);
    const float* qbase = &g_q[((size_t)bh * SS + qt * QROWS) * HD];
    for (int i = tid; i < QROWS * 16; i += 256) {
        int r = i >> 4, c4 = (i & 15) * 4;
        float4 v = *(const float4*)&qbase[r * HD + c4];
        v.x *= 0.125f; v.y *= 0.125f; v.z *= 0.125f; v.w *= 0.125f;  // pow2: stays tf32
        *(float4*)&Qs[r * ATS + c4] = v;
        float4 z = {0.f, 0.f, 0.f, 0.f};
        *(float4*)&Os[r * ATS + c4] = z;
    }
    if (tid < QROWS) { mrow[tid] = -1e30f; lrow[tid] = 0.f; }
    CP_WAIT0();
    __syncthreads();

    // Q fragments: this warp's 16 rows, loaded once
    wmma::fragment<wmma::matrix_a, 16, 16, 8, wmma::precision::tf32, wmma::row_major> qf[8];
#pragma unroll
    for (int ks = 0; ks < 8; ks++)
        wmma::load_matrix_sync(qf[ks], Qs + (wid * 16) * ATS + ks * 8, ATS);

    const int ntiles = 2 * qt + 2;       // k tiles of 64 rows covering 0..(qt+1)*128
    for (int kt = 0; kt < ntiles; kt++) {
        const int buf = kt & 1;
        if (kt + 1 < ntiles) issue_tile(kt + 1, buf ^ 1);

        const float* Ks = Kd[buf];
        const float* Vs = Vd[buf];
        float* sprow = SP + (wid * 16) * ATS;

        // ---- S = Q @ K^T  (this warp's 16 rows x all 64 cols) ----
        {
            wmma::fragment<wmma::accumulator, 16, 16, 8, float> sacc[4];
#pragma unroll
            for (int nt = 0; nt < 4; nt++) wmma::fill_fragment(sacc[nt], 0.f);
#pragma unroll
            for (int ks = 0; ks < 8; ks++) {
#pragma unroll
                for (int nt = 0; nt < 4; nt++) {
                    wmma::fragment<wmma::matrix_b, 16, 16, 8, wmma::precision::tf32, wmma::col_major> kf;
                    wmma::load_matrix_sync(kf, Ks + (nt * 16) * ATS + ks * 8, ATS);
                    wmma::mma_sync(sacc[nt], qf[ks], kf, sacc[nt]);
                }
            }
#pragma unroll
            for (int nt = 0; nt < 4; nt++)
                wmma::store_matrix_sync(sprow + nt * 16, sacc[nt], ATS, wmma::mem_row_major);
        }
        __syncwarp();

        // ---- warp-local online softmax: 2 lanes per row, 32 cols each ----
        {
            const int row  = wid * 16 + (lane >> 1);    // this warp's row
            const int half = lane & 1;
            float* srow = SP + row * ATS + half * 32;
            const int gr = qt * QROWS + row;             // global q row
            int jmaxRow = gr - kt * 64 + 1;              // causal limit in this tile
            jmaxRow = (jmaxRow < 0) ? 0 : (jmaxRow > 64 ? 64 : jmaxRow);
            int lim = jmaxRow - half * 32;
            lim = (lim < 0) ? 0 : (lim > 32 ? 32 : lim);

            float mx = -1e30f;
#pragma unroll 8
            for (int j = 0; j < 32; j++)
                if (j < lim) mx = fmaxf(mx, srow[j]);
            mx = fmaxf(mx, __shfl_xor_sync(0xffffffffu, mx, 1));
            const float mold = mrow[row];
            mx = fmaxf(mx, mold);
            const float alpha = __expf(mold - mx);

            float sum = 0.f;
#pragma unroll 8
            for (int j = 0; j < 32; j++) {
                float p = (j < lim) ? rtf(__expf(srow[j] - mx)) : 0.f;
                srow[j] = p;
                sum += p;
            }
            sum += __shfl_xor_sync(0xffffffffu, sum, 1);
            if (half == 0) { lrow[row] = lrow[row] * alpha + sum; mrow[row] = mx; }

            float* orow = Os + row * ATS + half * 32;
#pragma unroll
            for (int d = 0; d < 32; d += 4) {
                float4 o4 = *(float4*)&orow[d];
                o4.x *= alpha; o4.y *= alpha; o4.z *= alpha; o4.w *= alpha;
                *(float4*)&orow[d] = o4;
            }
        }
        __syncwarp();

        // ---- O += P @ V  (this warp's 16 rows) ----
        {
            wmma::fragment<wmma::matrix_a, 16, 16, 8, wmma::precision::tf32, wmma::row_major> pf[8];
#pragma unroll
            for (int ks = 0; ks < 8; ks++)
                wmma::load_matrix_sync(pf[ks], sprow + ks * 8, ATS);
#pragma unroll
            for (int nt = 0; nt < 4; nt++) {
                wmma::fragment<wmma::accumulator, 16, 16, 8, float> of;
                wmma::load_matrix_sync(of, Os + (wid * 16) * ATS + nt * 16, ATS, wmma::mem_row_major);
#pragma unroll
                for (int ks = 0; ks < 8; ks++) {
                    wmma::fragment<wmma::matrix_b, 16, 16, 8, wmma::precision::tf32, wmma::row_major> vf;
                    wmma::load_matrix_sync(vf, Vs + (ks * 8) * ATS + nt * 16, ATS);
                    wmma::mma_sync(of, pf[ks], vf, of);
                }
                wmma::store_matrix_sync(Os + (wid * 16) * ATS + nt * 16, of, ATS, wmma::mem_row_major);
            }
        }

        CP_WAIT0();            // next K/V tile landed
        __syncthreads();       // buffer rotation barrier (only CTA sync per tile)
    }

    // Normalize + write ctx (tf32-rounded: consumed by out-proj MMA)
    const int row  = tid >> 1;           // 0..127
    const int half = tid & 1;
    const float inv = 1.f / lrow[row];
    const int b = bh / HH, h = bh % HH;
    float* crow = &g_ctx[((size_t)b * SS + qt * QROWS + row) * DD + h * HD + half * 32];
    const float* orow = Os + row * ATS + half * 32;
#pragma unroll
    for (int d = 0; d < 32; d += 4) {
        float4 o4 = *(const float4*)&orow[d];
        o4.x *= inv; o4.y *= inv; o4.z *= inv; o4.w *= inv;
        *(float4*)&crow[d] = rtf4(o4);
    }
}

// ---------------------------------------------------------------------------
extern "C" void kernel_launch(void* const* d_in, const int* in_sizes, int n_in,
                              void* d_out, int out_size)
{
    const float* x  = (const float*)d_in[0];
    const float* Wq = (const float*)d_in[1];
    const float* bq = (const float*)d_in[2];
    const float* Wk = (const float*)d_in[3];
    const float* bk = (const float*)d_in[4];
    const float* Wv = (const float*)d_in[5];
    const float* bv = (const float*)d_in[6];
    const float* Wo = (const float*)d_in[7];
    const float* bo = (const float*)d_in[8];
    float* out = (float*)d_out;

    cudaFuncSetAttribute(gemm_wmma<true>,  cudaFuncAttributeMaxDynamicSharedMemorySize, SMEM_BYTES);
    cudaFuncSetAttribute(gemm_wmma<false>, cudaFuncAttributeMaxDynamicSharedMemorySize, SMEM_BYTES);
    cudaFuncSetAttribute(attn_wmma, cudaFuncAttributeMaxDynamicSharedMemorySize, ATT_SMEM_BYTES);

    conv_tf32<<<dim3(512, 1, 5), 256>>>(x, Wq, Wk, Wv, Wo);

    dim3 gqkv(DD / 128, NROWS / 128, 3);
    gemm_wmma<true><<<gqkv, 256, SMEM_BYTES>>>(bq, bk, bv, nullptr);

    dim3 gattn(SS / QROWS, BB * HH);          // (16, 32)
    attn_wmma<<<gattn, 256, ATT_SMEM_BYTES>>>();

    dim3 gout(DD / 128, NROWS / 128);
    gemm_wmma<false><<<gout, 256, SMEM_BYTES>>>(bo, nullptr, nullptr, out);
}

// round 15
// speedup vs baseline: 1.0381x; 1.0381x over previous
#include <cuda_runtime.h>
#include <cstdint>
#include <mma.h>

using namespace nvcuda;

#define BB 2
#define SS 2048
#define DD 1024
#define HH 16
#define HD 64
#define NROWS (BB*SS)

__device__ float g_q[NROWS*DD];        // [B,H,S,HD]  (tf32-rounded)
__device__ float g_k[NROWS*DD];        // [B,H,S,HD]  (tf32-rounded)
__device__ float g_v[NROWS*DD];        // [B,H,S,HD]  (tf32-rounded)
__device__ float g_ctx[NROWS*DD];      // [B,S,D]     (tf32-rounded)
__device__ float g_xt[NROWS*DD];       // tf32(x)
__device__ float g_wt4[4*DD*DD];       // tf32(Wq,Wk,Wv,Wo)

__device__ __forceinline__ uint32_t smem_u32(const void* p) {
    uint32_t a;
    asm("{ .reg .u64 t; cvta.to.shared.u64 t, %1; cvt.u32.u64 %0, t; }" : "=r"(a) : "l"(p));
    return a;
}
__device__ __forceinline__ float rtf(float x) {
    uint32_t u;
    asm("cvt.rna.tf32.f32 %0, %1;" : "=r"(u) : "f"(x));
    return __uint_as_float(u);
}
__device__ __forceinline__ float4 rtf4(float4 v) {
    v.x = rtf(v.x); v.y = rtf(v.y); v.z = rtf(v.z); v.w = rtf(v.w);
    return v;
}
#define CP_ASYNC16(s, g) \
    asm volatile("cp.async.cg.shared.global [%0], [%1], 16;" :: "r"(s), "l"(g))
#define CP_COMMIT() asm volatile("cp.async.commit_group;")
#define CP_WAIT0()  asm volatile("cp.async.wait_group 0;" ::: "memory")

// mma.sync m16n8k8 tf32: PTX-documented fragment layout (g=lane>>2, q=lane&3):
//  A: a0=(g,q) a1=(g+8,q) a2=(g,q+4) a3=(g+8,q+4)
//  B: b0=(k=q,n=g) b1=(k=q+4,n=g)
//  C: c0=(g,2q) c1=(g,2q+1) c2=(g+8,2q) c3=(g+8,2q+1)
__device__ __forceinline__ void mma8(float* d, const uint32_t* a, uint32_t b0, uint32_t b1) {
    asm volatile(
        "mma.sync.aligned.m16n8k8.row.col.f32.tf32.tf32.f32 "
        "{%0,%1,%2,%3}, {%4,%5,%6,%7}, {%8,%9}, {%0,%1,%2,%3};"
        : "+f"(d[0]), "+f"(d[1]), "+f"(d[2]), "+f"(d[3])
        : "r"(a[0]), "r"(a[1]), "r"(a[2]), "r"(a[3]), "r"(b0), "r"(b1));
}

// ---------------------------------------------------------------------------
// Pre-convert x and all W to tf32-rounded copies
// ---------------------------------------------------------------------------
__global__ __launch_bounds__(256) void conv_tf32(
    const float* __restrict__ x,
    const float* __restrict__ Wq, const float* __restrict__ Wk,
    const float* __restrict__ Wv, const float* __restrict__ Wo)
{
    const int z = blockIdx.z;
    const float* src; float* dst; int n4;
    if (z == 0)      { src = x;  dst = g_xt;              n4 = NROWS * DD / 4; }
    else if (z == 1) { src = Wq; dst = g_wt4;             n4 = DD * DD / 4; }
    else if (z == 2) { src = Wk; dst = g_wt4 + DD * DD;   n4 = DD * DD / 4; }
    else if (z == 3) { src = Wv; dst = g_wt4 + 2*DD*DD;   n4 = DD * DD / 4; }
    else             { src = Wo; dst = g_wt4 + 3*DD*DD;   n4 = DD * DD / 4; }
    const int stride = gridDim.x * blockDim.x;
    for (int i = blockIdx.x * blockDim.x + threadIdx.x; i < n4; i += stride)
        *(float4*)&dst[i * 4] = rtf4(*(const float4*)&src[i * 4]);
}

// ---------------------------------------------------------------------------
// tf32 WMMA GEMM (unchanged from best R12)
// ---------------------------------------------------------------------------
#define AS_STRIDE 36
#define BS_STRIDE 136
#define AS_FLOATS (128 * AS_STRIDE)
#define BS_FLOATS (32 * BS_STRIDE)
#define SMEM_BYTES  (2 * (AS_FLOATS + BS_FLOATS) * 4)   // 71680
#define ST_STRIDE 132

template<bool SCATTER>
__global__ __launch_bounds__(256, 2) void gemm_wmma(
    const float* __restrict__ bi0, const float* __restrict__ bi1, const float* __restrict__ bi2,
    float* __restrict__ Yout)
{
    extern __shared__ float smem[];
    float* sA = smem;
    float* sB = smem + 2 * AS_FLOATS;

    const int tid  = threadIdx.x;
    const int wid  = tid >> 5;
    const int wm   = wid & 1;
    const int wn   = wid >> 1;

    const float* __restrict__ A = SCATTER ? g_xt : g_ctx;
    const float* __restrict__ W;
    const float* __restrict__ bias;
    float* __restrict__ outp;
    if (SCATTER) {
        const int z = blockIdx.z;
        W    = g_wt4 + (size_t)z * DD * DD;
        bias = (z == 0) ? bi0 : (z == 1) ? bi1 : bi2;
        outp = (z == 0) ? g_q : (z == 1) ? g_k : g_v;
    } else {
        W = g_wt4 + (size_t)3 * DD * DD; bias = bi0; outp = Yout;
    }

    const int rowBase = blockIdx.y * 128;
    const int colBase = blockIdx.x * 128;

    wmma::fragment<wmma::accumulator, 16, 16, 8, float> acc[4][2];
#pragma unroll
    for (int mt = 0; mt < 4; mt++)
#pragma unroll
        for (int nt = 0; nt < 2; nt++)
            wmma::fill_fragment(acc[mt][nt], 0.f);

    const uint32_t sAu = smem_u32(sA);
    const uint32_t sBu = smem_u32(sB);

    auto load_tile = [&](int it, int buf) {
        const int k0 = it * 32;
        uint32_t aBase = sAu + buf * AS_FLOATS * 4;
        uint32_t bBase = sBu + buf * BS_FLOATS * 4;
#pragma unroll
        for (int i = 0; i < 4; i++) {
            int ch = tid + i * 256;
            int m = ch >> 3, kq = ch & 7;
            CP_ASYNC16(aBase + (m * AS_STRIDE + kq * 4) * 4,
                       &A[(size_t)(rowBase + m) * DD + k0 + kq * 4]);
        }
#pragma unroll
        for (int i = 0; i < 4; i++) {
            int ch = tid + i * 256;
            int kk = ch >> 5, nq = ch & 31;
            CP_ASYNC16(bBase + (kk * BS_STRIDE + nq * 4) * 4,
                       &W[(size_t)(k0 + kk) * DD + colBase + nq * 4]);
        }
        CP_COMMIT();
    };

    load_tile(0, 0);
    CP_WAIT0();
    __syncthreads();

    const int NT = DD / 32;
    for (int it = 0; it < NT; it++) {
        const int buf = it & 1;
        if (it + 1 < NT) load_tile(it + 1, buf ^ 1);

        const float* As = sA + buf * AS_FLOATS;
        const float* Bs = sB + buf * BS_FLOATS;

#pragma unroll
        for (int ks = 0; ks < 4; ks++) {
            const int k = ks * 8;
            wmma::fragment<wmma::matrix_a, 16, 16, 8, wmma::precision::tf32, wmma::row_major> af[4];
            wmma::fragment<wmma::matrix_b, 16, 16, 8, wmma::precision::tf32, wmma::row_major> bf[2];
#pragma unroll
            for (int mt = 0; mt < 4; mt++)
                wmma::load_matrix_sync(af[mt], As + (wm * 64 + mt * 16) * AS_STRIDE + k, AS_STRIDE);
#pragma unroll
            for (int nt = 0; nt < 2; nt++)
                wmma::load_matrix_sync(bf[nt], Bs + k * BS_STRIDE + wn * 32 + nt * 16, BS_STRIDE);
#pragma unroll
            for (int mt = 0; mt < 4; mt++)
#pragma unroll
                for (int nt = 0; nt < 2; nt++)
                    wmma::mma_sync(acc[mt][nt], af[mt], bf[nt], acc[mt][nt]);
        }

        if (it + 1 < NT) CP_WAIT0();
        __syncthreads();
    }

    float* stage = smem;
#pragma unroll
    for (int mt = 0; mt < 4; mt++)
#pragma unroll
        for (int nt = 0; nt < 2; nt++)
            wmma::store_matrix_sync(stage + (wm * 64 + mt * 16) * ST_STRIDE + wn * 32 + nt * 16,
                                    acc[mt][nt], ST_STRIDE, wmma::mem_row_major);
    __syncthreads();

    const int rr   = tid >> 1;
    const int half = tid & 1;
    const int row  = rowBase + rr;
    const int bb   = row >> 11;
    const int s    = row & (SS - 1);
    if (SCATTER) {
        const int colG = colBase + half * 64;
        const int h = colG >> 6;
        float* dst = &outp[(((size_t)(bb * HH + h)) * SS + s) * HD];
#pragma unroll
        for (int j = 0; j < 16; j++) {
            const int cl = half * 64 + j * 4;
            float4 v  = *(const float4*)&stage[rr * ST_STRIDE + cl];
            float4 bv = *(const float4*)&bias[colBase + cl];
            v.x += bv.x; v.y += bv.y; v.z += bv.z; v.w += bv.w;
            *(float4*)&dst[j * 4] = rtf4(v);
        }
    } else {
        float* dst = &outp[(size_t)row * DD + colBase];
#pragma unroll
        for (int j = 0; j < 16; j++) {
            const int cl = half * 64 + j * 4;
            float4 v  = *(const float4*)&stage[rr * ST_STRIDE + cl];
            float4 bv = *(const float4*)&bias[colBase + cl];
            v.x += bv.x; v.y += bv.y; v.z += bv.z; v.w += bv.w;
            *(float4*)&dst[cl] = v;
        }
    }
}

// ---------------------------------------------------------------------------
// Flash attention v5 — raw mma.sync, fully register-resident S and O.
// CTA = (qt, bh): 64 q rows, 128 thr / 4 warps; warp w owns rows w*16..+15.
// K,V smem tiles [s][hd] stride 68 (bank-conflict-free for all frag loads).
// Softmax in registers (quad shfl). O acc in registers across tiles.
// ---------------------------------------------------------------------------
#define ATS 68
#define TILE_F (64 * ATS)                 // 4352 floats
#define ATT_SMEM_BYTES (5 * TILE_F * 4)   // Qs + K0,K1,V0,V1 = 87040

__global__ __launch_bounds__(128) void attn_mma()
{
    extern __shared__ float sm[];
    float* Qs = sm;
    float* Kd[2] = { sm + TILE_F,     sm + 2 * TILE_F };
    float* Vd[2] = { sm + 3 * TILE_F, sm + 4 * TILE_F };

    const int qt   = (int)gridDim.x - 1 - (int)blockIdx.x;   // heavy-first
    const int bh   = blockIdx.y;
    const int tid  = threadIdx.x;
    const int wid  = tid >> 5;
    const int lane = tid & 31;
    const int g    = lane >> 2;          // 0..7
    const int q    = lane & 3;           // 0..3

    const uint32_t ku[2] = { smem_u32(Kd[0]), smem_u32(Kd[1]) };
    const uint32_t vu[2] = { smem_u32(Vd[0]), smem_u32(Vd[1]) };
    const float* kbase0 = &g_k[(size_t)bh * SS * HD];
    const float* vbase0 = &g_v[(size_t)bh * SS * HD];

    auto issue_tile = [&](int kt, int buf) {
        const float* kb = kbase0 + (size_t)kt * 64 * HD;
        const float* vb = vbase0 + (size_t)kt * 64 * HD;
#pragma unroll
        for (int i = 0; i < 8; i++) {
            int ch = tid + i * 128;                  // 1024 chunks
            int r = ch >> 4, c4 = (ch & 15) * 4;
            CP_ASYNC16(ku[buf] + (r * ATS + c4) * 4, kb + r * HD + c4);
        }
#pragma unroll
        for (int i = 0; i < 8; i++) {
            int ch = tid + i * 128;
            int r = ch >> 4, c4 = (ch & 15) * 4;
            CP_ASYNC16(vu[buf] + (r * ATS + c4) * 4, vb + r * HD + c4);
        }
        CP_COMMIT();
    };

    // Prologue: issue K/V tile 0; stage Q (scaled) to smem
    issue_tile(0, 0);
    const float* qbase = &g_q[((size_t)bh * SS + (size_t)qt * 64) * HD];
    for (int i = tid; i < 1024; i += 128) {
        int r = i >> 4, c4 = (i & 15) * 4;
        float4 v = *(const float4*)&qbase[r * HD + c4];
        v.x *= 0.125f; v.y *= 0.125f; v.z *= 0.125f; v.w *= 0.125f;   // pow2: stays tf32
        *(float4*)&Qs[r * ATS + c4] = v;
    }
    CP_WAIT0();
    __syncthreads();

    // Q A-fragments for this warp's 16 rows (8 k-steps), loaded once
    uint32_t qa[8][4];
    {
        const float* Qw = Qs + (wid * 16) * ATS;
#pragma unroll
        for (int ks = 0; ks < 8; ks++) {
            qa[ks][0] = __float_as_uint(Qw[(g    ) * ATS + ks * 8 + q    ]);
            qa[ks][1] = __float_as_uint(Qw[(g + 8) * ATS + ks * 8 + q    ]);
            qa[ks][2] = __float_as_uint(Qw[(g    ) * ATS + ks * 8 + q + 4]);
            qa[ks][3] = __float_as_uint(Qw[(g + 8) * ATS + ks * 8 + q + 4]);
        }
    }

    float oc[8][4];
#pragma unroll
    for (int t = 0; t < 8; t++) { oc[t][0] = oc[t][1] = oc[t][2] = oc[t][3] = 0.f; }
    float m0 = -1e30f, m1 = -1e30f, l0 = 0.f, l1 = 0.f;

    for (int kt = 0; kt <= qt; kt++) {
        const int buf = kt & 1;
        if (kt < qt) issue_tile(kt + 1, buf ^ 1);

        const float* Ks = Kd[buf];
        const float* Vs = Vd[buf];

        // ---- S = Q @ K^T : 16x64, in registers ----
        float sc[8][4];
#pragma unroll
        for (int t = 0; t < 8; t++) { sc[t][0] = sc[t][1] = sc[t][2] = sc[t][3] = 0.f; }
#pragma unroll
        for (int ks = 0; ks < 8; ks++) {
#pragma unroll
            for (int t = 0; t < 8; t++) {
                // B(k,n)=K[n][k]: b0=K[t*8+g][ks*8+q], b1=+4  (conflict-free)
                uint32_t b0 = __float_as_uint(Ks[(t * 8 + g) * ATS + ks * 8 + q    ]);
                uint32_t b1 = __float_as_uint(Ks[(t * 8 + g) * ATS + ks * 8 + q + 4]);
                mma8(sc[t], qa[ks], b0, b1);
            }
        }

        // ---- causal mask (diagonal tile only) ----
        if (kt == qt) {
            const int r0 = wid * 16 + g, r1 = r0 + 8;
#pragma unroll
            for (int t = 0; t < 8; t++) {
                const int c0 = t * 8 + 2 * q, c1 = c0 + 1;
                if (c0 > r0) sc[t][0] = -1e30f;
                if (c1 > r0) sc[t][1] = -1e30f;
                if (c0 > r1) sc[t][2] = -1e30f;
                if (c1 > r1) sc[t][3] = -1e30f;
            }
        }

        // ---- in-register online softmax (rows g and g+8) ----
        {
            float mx0 = m0, mx1 = m1;
#pragma unroll
            for (int t = 0; t < 8; t++) {
                mx0 = fmaxf(mx0, fmaxf(sc[t][0], sc[t][1]));
                mx1 = fmaxf(mx1, fmaxf(sc[t][2], sc[t][3]));
            }
            mx0 = fmaxf(mx0, __shfl_xor_sync(0xffffffffu, mx0, 1));
            mx0 = fmaxf(mx0, __shfl_xor_sync(0xffffffffu, mx0, 2));
            mx1 = fmaxf(mx1, __shfl_xor_sync(0xffffffffu, mx1, 1));
            mx1 = fmaxf(mx1, __shfl_xor_sync(0xffffffffu, mx1, 2));

            const float a0 = __expf(m0 - mx0);
            const float a1 = __expf(m1 - mx1);
            float s0 = 0.f, s1 = 0.f;
#pragma unroll
            for (int t = 0; t < 8; t++) {
                float p;
                p = rtf(__expf(sc[t][0] - mx0)); sc[t][0] = p; s0 += p;
                p = rtf(__expf(sc[t][1] - mx0)); sc[t][1] = p; s0 += p;
                p = rtf(__expf(sc[t][2] - mx1)); sc[t][2] = p; s1 += p;
                p = rtf(__expf(sc[t][3] - mx1)); sc[t][3] = p; s1 += p;
            }
            s0 += __shfl_xor_sync(0xffffffffu, s0, 1);
            s0 += __shfl_xor_sync(0xffffffffu, s0, 2);
            s1 += __shfl_xor_sync(0xffffffffu, s1, 1);
            s1 += __shfl_xor_sync(0xffffffffu, s1, 2);
            l0 = l0 * a0 + s0;  l1 = l1 * a1 + s1;
            m0 = mx0;           m1 = mx1;
#pragma unroll
            for (int t = 0; t < 8; t++) {
                oc[t][0] *= a0; oc[t][1] *= a0;
                oc[t][2] *= a1; oc[t][3] *= a1;
            }
        }

        // ---- O += P @ V : P acc-layout -> A-frag via quad shfl ----
        const int srcA = (lane & ~3) | (q >> 1);     // holds cols 2q',2q'+1
        const int srcB = srcA + 2;                   // cols (q+4) source
        const bool odd = (q & 1);
#pragma unroll
        for (int j = 0; j < 8; j++) {
            float v00 = __shfl_sync(0xffffffffu, sc[j][0], srcA);
            float v01 = __shfl_sync(0xffffffffu, sc[j][1], srcA);
            float v20 = __shfl_sync(0xffffffffu, sc[j][2], srcA);
            float v21 = __shfl_sync(0xffffffffu, sc[j][3], srcA);
            float w00 = __shfl_sync(0xffffffffu, sc[j][0], srcB);
            float w01 = __shfl_sync(0xffffffffu, sc[j][1], srcB);
            float w20 = __shfl_sync(0xffffffffu, sc[j][2], srcB);
            float w21 = __shfl_sync(0xffffffffu, sc[j][3], srcB);
            uint32_t pa[4];
            pa[0] = __float_as_uint(odd ? v01 : v00);   // (g,   j*8+q)
            pa[1] = __float_as_uint(odd ? v21 : v20);   // (g+8, j*8+q)
            pa[2] = __float_as_uint(odd ? w01 : w00);   // (g,   j*8+q+4)
            pa[3] = __float_as_uint(odd ? w21 : w20);   // (g+8, j*8+q+4)
#pragma unroll
            for (int t = 0; t < 8; t++) {
                // B(k,n)=V[k][n]: b0=V[j*8+q][t*8+g], b1=V[j*8+q+4][t*8+g]
                uint32_t b0 = __float_as_uint(Vs[(j * 8 + q    ) * ATS + t * 8 + g]);
                uint32_t b1 = __float_as_uint(Vs[(j * 8 + q + 4) * ATS + t * 8 + g]);
                mma8(oc[t], pa, b0, b1);
            }
        }

        CP_WAIT0();            // next K/V tile landed
        __syncthreads();       // buffer rotation
    }

    // ---- epilogue: normalize, round, write ctx ----
    const float inv0 = 1.f / l0, inv1 = 1.f / l1;
    const int b = bh / HH, h = bh % HH;
    const int row0 = qt * 64 + wid * 16 + g;
    float* base = &g_ctx[((size_t)b * SS + row0) * DD + h * HD];
#pragma unroll
    for (int t = 0; t < 8; t++) {
        float2 w0, w1;
        w0.x = rtf(oc[t][0] * inv0); w0.y = rtf(oc[t][1] * inv0);
        w1.x = rtf(oc[t][2] * inv1); w1.y = rtf(oc[t][3] * inv1);
        *(float2*)&base[t * 8 + 2 * q] = w0;
        *(float2*)&base[(size_t)8 * DD + t * 8 + 2 * q] = w1;
    }
}

// ---------------------------------------------------------------------------
extern "C" void kernel_launch(void* const* d_in, const int* in_sizes, int n_in,
                              void* d_out, int out_size)
{
    const float* x  = (const float*)d_in[0];
    const float* Wq = (const float*)d_in[1];
    const float* bq = (const float*)d_in[2];
    const float* Wk = (const float*)d_in[3];
    const float* bk = (const float*)d_in[4];
    const float* Wv = (const float*)d_in[5];
    const float* bv = (const float*)d_in[6];
    const float* Wo = (const float*)d_in[7];
    const float* bo = (const float*)d_in[8];
    float* out = (float*)d_out;

    cudaFuncSetAttribute(gemm_wmma<true>,  cudaFuncAttributeMaxDynamicSharedMemorySize, SMEM_BYTES);
    cudaFuncSetAttribute(gemm_wmma<false>, cudaFuncAttributeMaxDynamicSharedMemorySize, SMEM_BYTES);
    cudaFuncSetAttribute(attn_mma, cudaFuncAttributeMaxDynamicSharedMemorySize, ATT_SMEM_BYTES);

    conv_tf32<<<dim3(512, 1, 5), 256>>>(x, Wq, Wk, Wv, Wo);

    dim3 gqkv(DD / 128, NROWS / 128, 3);
    gemm_wmma<true><<<gqkv, 256, SMEM_BYTES>>>(bq, bk, bv, nullptr);

    dim3 gattn(SS / 64, BB * HH);             // (32, 32)
    attn_mma<<<gattn, 128, ATT_SMEM_BYTES>>>();

    dim3 gout(DD / 128, NROWS / 128);
    gemm_wmma<false><<<gout, 256, SMEM_BYTES>>>(bo, nullptr, nullptr, out);
}

// round 16
// speedup vs baseline: 1.5830x; 1.5249x over previous
#include <cuda_runtime.h>
#include <cstdint>
#include <mma.h>

using namespace nvcuda;

#define BB 2
#define SS 2048
#define DD 1024
#define HH 16
#define HD 64
#define NROWS (BB*SS)

__device__ float g_q[NROWS*DD];        // [B,H,S,HD]  (tf32-rounded)
__device__ float g_k[NROWS*DD];        // [B,H,S,HD]  (tf32-rounded)
__device__ float g_v[NROWS*DD];        // [B,H,S,HD]  (tf32-rounded)
__device__ float g_ctx[NROWS*DD];      // [B,S,D]     (tf32-rounded)
__device__ float g_xt[NROWS*DD];       // tf32(x)
__device__ float g_wt4[4*DD*DD];       // tf32(Wq,Wk,Wv,Wo)

__device__ __forceinline__ uint32_t smem_u32(const void* p) {
    uint32_t a;
    asm("{ .reg .u64 t; cvta.to.shared.u64 t, %1; cvt.u32.u64 %0, t; }" : "=r"(a) : "l"(p));
    return a;
}
__device__ __forceinline__ float rtf(float x) {
    uint32_t u;
    asm("cvt.rna.tf32.f32 %0, %1;" : "=r"(u) : "f"(x));
    return __uint_as_float(u);
}
__device__ __forceinline__ float4 rtf4(float4 v) {
    v.x = rtf(v.x); v.y = rtf(v.y); v.z = rtf(v.z); v.w = rtf(v.w);
    return v;
}
#define CP_ASYNC16(s, g) \
    asm volatile("cp.async.cg.shared.global [%0], [%1], 16;" :: "r"(s), "l"(g))
#define CP_COMMIT() asm volatile("cp.async.commit_group;")
#define CP_WAIT0()  asm volatile("cp.async.wait_group 0;" ::: "memory")

// mma.sync m16n8k8 tf32 fragment layout (g=lane>>2, q=lane&3):
//  A: a0=(g,q) a1=(g+8,q) a2=(g,q+4) a3=(g+8,q+4)
//  B: b0=(k=q,n=g) b1=(k=q+4,n=g)
//  C: c0=(g,2q) c1=(g,2q+1) c2=(g+8,2q) c3=(g+8,2q+1)
__device__ __forceinline__ void mma8(float* d, const uint32_t* a, uint32_t b0, uint32_t b1) {
    asm volatile(
        "mma.sync.aligned.m16n8k8.row.col.f32.tf32.tf32.f32 "
        "{%0,%1,%2,%3}, {%4,%5,%6,%7}, {%8,%9}, {%0,%1,%2,%3};"
        : "+f"(d[0]), "+f"(d[1]), "+f"(d[2]), "+f"(d[3])
        : "r"(a[0]), "r"(a[1]), "r"(a[2]), "r"(a[3]), "r"(b0), "r"(b1));
}

// ---------------------------------------------------------------------------
// Pre-convert x and all W to tf32-rounded copies
// ---------------------------------------------------------------------------
__global__ __launch_bounds__(256) void conv_tf32(
    const float* __restrict__ x,
    const float* __restrict__ Wq, const float* __restrict__ Wk,
    const float* __restrict__ Wv, const float* __restrict__ Wo)
{
    const int z = blockIdx.z;
    const float* src; float* dst; int n4;
    if (z == 0)      { src = x;  dst = g_xt;              n4 = NROWS * DD / 4; }
    else if (z == 1) { src = Wq; dst = g_wt4;             n4 = DD * DD / 4; }
    else if (z == 2) { src = Wk; dst = g_wt4 + DD * DD;   n4 = DD * DD / 4; }
    else if (z == 3) { src = Wv; dst = g_wt4 + 2*DD*DD;   n4 = DD * DD / 4; }
    else             { src = Wo; dst = g_wt4 + 3*DD*DD;   n4 = DD * DD / 4; }
    const int stride = gridDim.x * blockDim.x;
    for (int i = blockIdx.x * blockDim.x + threadIdx.x; i < n4; i += stride)
        *(float4*)&dst[i * 4] = rtf4(*(const float4*)&src[i * 4]);
}

// ---------------------------------------------------------------------------
// tf32 WMMA GEMM (unchanged from best R12)
// ---------------------------------------------------------------------------
#define AS_STRIDE 36
#define BS_STRIDE 136
#define AS_FLOATS (128 * AS_STRIDE)
#define BS_FLOATS (32 * BS_STRIDE)
#define SMEM_BYTES  (2 * (AS_FLOATS + BS_FLOATS) * 4)   // 71680
#define ST_STRIDE 132

template<bool SCATTER>
__global__ __launch_bounds__(256, 2) void gemm_wmma(
    const float* __restrict__ bi0, const float* __restrict__ bi1, const float* __restrict__ bi2,
    float* __restrict__ Yout)
{
    extern __shared__ float smem[];
    float* sA = smem;
    float* sB = smem + 2 * AS_FLOATS;

    const int tid  = threadIdx.x;
    const int wid  = tid >> 5;
    const int wm   = wid & 1;
    const int wn   = wid >> 1;

    const float* __restrict__ A = SCATTER ? g_xt : g_ctx;
    const float* __restrict__ W;
    const float* __restrict__ bias;
    float* __restrict__ outp;
    if (SCATTER) {
        const int z = blockIdx.z;
        W    = g_wt4 + (size_t)z * DD * DD;
        bias = (z == 0) ? bi0 : (z == 1) ? bi1 : bi2;
        outp = (z == 0) ? g_q : (z == 1) ? g_k : g_v;
    } else {
        W = g_wt4 + (size_t)3 * DD * DD; bias = bi0; outp = Yout;
    }

    const int rowBase = blockIdx.y * 128;
    const int colBase = blockIdx.x * 128;

    wmma::fragment<wmma::accumulator, 16, 16, 8, float> acc[4][2];
#pragma unroll
    for (int mt = 0; mt < 4; mt++)
#pragma unroll
        for (int nt = 0; nt < 2; nt++)
            wmma::fill_fragment(acc[mt][nt], 0.f);

    const uint32_t sAu = smem_u32(sA);
    const uint32_t sBu = smem_u32(sB);

    auto load_tile = [&](int it, int buf) {
        const int k0 = it * 32;
        uint32_t aBase = sAu + buf * AS_FLOATS * 4;
        uint32_t bBase = sBu + buf * BS_FLOATS * 4;
#pragma unroll
        for (int i = 0; i < 4; i++) {
            int ch = tid + i * 256;
            int m = ch >> 3, kq = ch & 7;
            CP_ASYNC16(aBase + (m * AS_STRIDE + kq * 4) * 4,
                       &A[(size_t)(rowBase + m) * DD + k0 + kq * 4]);
        }
#pragma unroll
        for (int i = 0; i < 4; i++) {
            int ch = tid + i * 256;
            int kk = ch >> 5, nq = ch & 31;
            CP_ASYNC16(bBase + (kk * BS_STRIDE + nq * 4) * 4,
                       &W[(size_t)(k0 + kk) * DD + colBase + nq * 4]);
        }
        CP_COMMIT();
    };

    load_tile(0, 0);
    CP_WAIT0();
    __syncthreads();

    const int NT = DD / 32;
    for (int it = 0; it < NT; it++) {
        const int buf = it & 1;
        if (it + 1 < NT) load_tile(it + 1, buf ^ 1);

        const float* As = sA + buf * AS_FLOATS;
        const float* Bs = sB + buf * BS_FLOATS;

#pragma unroll
        for (int ks = 0; ks < 4; ks++) {
            const int k = ks * 8;
            wmma::fragment<wmma::matrix_a, 16, 16, 8, wmma::precision::tf32, wmma::row_major> af[4];
            wmma::fragment<wmma::matrix_b, 16, 16, 8, wmma::precision::tf32, wmma::row_major> bf[2];
#pragma unroll
            for (int mt = 0; mt < 4; mt++)
                wmma::load_matrix_sync(af[mt], As + (wm * 64 + mt * 16) * AS_STRIDE + k, AS_STRIDE);
#pragma unroll
            for (int nt = 0; nt < 2; nt++)
                wmma::load_matrix_sync(bf[nt], Bs + k * BS_STRIDE + wn * 32 + nt * 16, BS_STRIDE);
#pragma unroll
            for (int mt = 0; mt < 4; mt++)
#pragma unroll
                for (int nt = 0; nt < 2; nt++)
                    wmma::mma_sync(acc[mt][nt], af[mt], bf[nt], acc[mt][nt]);
        }

        if (it + 1 < NT) CP_WAIT0();
        __syncthreads();
    }

    float* stage = smem;
#pragma unroll
    for (int mt = 0; mt < 4; mt++)
#pragma unroll
        for (int nt = 0; nt < 2; nt++)
            wmma::store_matrix_sync(stage + (wm * 64 + mt * 16) * ST_STRIDE + wn * 32 + nt * 16,
                                    acc[mt][nt], ST_STRIDE, wmma::mem_row_major);
    __syncthreads();

    const int rr   = tid >> 1;
    const int half = tid & 1;
    const int row  = rowBase + rr;
    const int bb   = row >> 11;
    const int s    = row & (SS - 1);
    if (SCATTER) {
        const int colG = colBase + half * 64;
        const int h = colG >> 6;
        float* dst = &outp[(((size_t)(bb * HH + h)) * SS + s) * HD];
#pragma unroll
        for (int j = 0; j < 16; j++) {
            const int cl = half * 64 + j * 4;
            float4 v  = *(const float4*)&stage[rr * ST_STRIDE + cl];
            float4 bv = *(const float4*)&bias[colBase + cl];
            v.x += bv.x; v.y += bv.y; v.z += bv.z; v.w += bv.w;
            *(float4*)&dst[j * 4] = rtf4(v);
        }
    } else {
        float* dst = &outp[(size_t)row * DD + colBase];
#pragma unroll
        for (int j = 0; j < 16; j++) {
            const int cl = half * 64 + j * 4;
            float4 v  = *(const float4*)&stage[rr * ST_STRIDE + cl];
            float4 bv = *(const float4*)&bias[colBase + cl];
            v.x += bv.x; v.y += bv.y; v.z += bv.z; v.w += bv.w;
            *(float4*)&dst[cl] = v;
        }
    }
}

// ---------------------------------------------------------------------------
// Flash attention v6 — register-resident S/O (as v5), but 128 q rows / CTA,
// 256 threads / 8 warps -> 2 CTAs/SM = 4 warps/SMSP (2x latency hiding).
// Warps skip k-tiles entirely above their rows (warp-uniform causal skip).
// ---------------------------------------------------------------------------
#define ATS 68
#define KTILE_F (64 * ATS)                 // 4352 floats
#define QTILE_F (128 * ATS)                // 8704 floats
#define ATT_SMEM_BYTES ((QTILE_F + 4 * KTILE_F) * 4)   // 104448

__global__ __launch_bounds__(256, 2) void attn_mma()
{
    extern __shared__ float sm[];
    float* Qs = sm;
    float* Kd[2] = { sm + QTILE_F,               sm + QTILE_F + KTILE_F };
    float* Vd[2] = { sm + QTILE_F + 2 * KTILE_F, sm + QTILE_F + 3 * KTILE_F };

    const int qt   = (int)gridDim.x - 1 - (int)blockIdx.x;   // heavy-first
    const int bh   = blockIdx.y;
    const int tid  = threadIdx.x;
    const int wid  = tid >> 5;           // warp owns rows wid*16..+15
    const int lane = tid & 31;
    const int g    = lane >> 2;          // 0..7
    const int q    = lane & 3;           // 0..3

    const uint32_t ku[2] = { smem_u32(Kd[0]), smem_u32(Kd[1]) };
    const uint32_t vu[2] = { smem_u32(Vd[0]), smem_u32(Vd[1]) };
    const float* kbase0 = &g_k[(size_t)bh * SS * HD];
    const float* vbase0 = &g_v[(size_t)bh * SS * HD];

    auto issue_tile = [&](int kt, int buf) {
        const float* kb = kbase0 + (size_t)kt * 64 * HD;
        const float* vb = vbase0 + (size_t)kt * 64 * HD;
#pragma unroll
        for (int i = 0; i < 4; i++) {
            int ch = tid + i * 256;                  // 1024 chunks (64x16 float4)
            int r = ch >> 4, c4 = (ch & 15) * 4;
            CP_ASYNC16(ku[buf] + (r * ATS + c4) * 4, kb + r * HD + c4);
        }
#pragma unroll
        for (int i = 0; i < 4; i++) {
            int ch = tid + i * 256;
            int r = ch >> 4, c4 = (ch & 15) * 4;
            CP_ASYNC16(vu[buf] + (r * ATS + c4) * 4, vb + r * HD + c4);
        }
        CP_COMMIT();
    };

    // Prologue: issue K/V tile 0; stage Q (scaled) to smem
    issue_tile(0, 0);
    const float* qbase = &g_q[((size_t)bh * SS + (size_t)qt * 128) * HD];
    for (int i = tid; i < 2048; i += 256) {          // 128 rows x 16 float4
        int r = i >> 4, c4 = (i & 15) * 4;
        float4 v = *(const float4*)&qbase[r * HD + c4];
        v.x *= 0.125f; v.y *= 0.125f; v.z *= 0.125f; v.w *= 0.125f;   // pow2: stays tf32
        *(float4*)&Qs[r * ATS + c4] = v;
    }
    CP_WAIT0();
    __syncthreads();

    // Q A-fragments for this warp's 16 rows (8 k-steps), loaded once
    uint32_t qa[8][4];
    {
        const float* Qw = Qs + (wid * 16) * ATS;
#pragma unroll
        for (int ks = 0; ks < 8; ks++) {
            qa[ks][0] = __float_as_uint(Qw[(g    ) * ATS + ks * 8 + q    ]);
            qa[ks][1] = __float_as_uint(Qw[(g + 8) * ATS + ks * 8 + q    ]);
            qa[ks][2] = __float_as_uint(Qw[(g    ) * ATS + ks * 8 + q + 4]);
            qa[ks][3] = __float_as_uint(Qw[(g + 8) * ATS + ks * 8 + q + 4]);
        }
    }

    float oc[8][4];
#pragma unroll
    for (int t = 0; t < 8; t++) { oc[t][0] = oc[t][1] = oc[t][2] = oc[t][3] = 0.f; }
    float m0 = -1e30f, m1 = -1e30f, l0 = 0.f, l1 = 0.f;

    const int rowW  = qt * 128 + wid * 16;   // warp's first global q row
    const int row0g = rowW + g;              // this thread's row pair
    const int row1g = row0g + 8;

    const int ntiles = 2 * qt + 2;           // 64-row k tiles covering (qt+1)*128
    for (int kt = 0; kt < ntiles; kt++) {
        const int buf = kt & 1;
        if (kt + 1 < ntiles) issue_tile(kt + 1, buf ^ 1);

        // warp-uniform causal skip: tile entirely above this warp's rows
        if (kt * 64 <= rowW + 15) {
            const float* Ks = Kd[buf];
            const float* Vs = Vd[buf];

            // ---- S = Q @ K^T : 16x64, in registers ----
            float sc[8][4];
#pragma unroll
            for (int t = 0; t < 8; t++) { sc[t][0] = sc[t][1] = sc[t][2] = sc[t][3] = 0.f; }
#pragma unroll
            for (int ks = 0; ks < 8; ks++) {
#pragma unroll
                for (int t = 0; t < 8; t++) {
                    uint32_t b0 = __float_as_uint(Ks[(t * 8 + g) * ATS + ks * 8 + q    ]);
                    uint32_t b1 = __float_as_uint(Ks[(t * 8 + g) * ATS + ks * 8 + q + 4]);
                    mma8(sc[t], qa[ks], b0, b1);
                }
            }

            // ---- causal mask (tiles overlapping the diagonal) ----
            if (kt * 64 + 63 > rowW) {
                const int cb = kt * 64;
#pragma unroll
                for (int t = 0; t < 8; t++) {
                    const int c0 = cb + t * 8 + 2 * q, c1 = c0 + 1;
                    if (c0 > row0g) sc[t][0] = -1e30f;
                    if (c1 > row0g) sc[t][1] = -1e30f;
                    if (c0 > row1g) sc[t][2] = -1e30f;
                    if (c1 > row1g) sc[t][3] = -1e30f;
                }
            }

            // ---- in-register online softmax (rows g and g+8) ----
            {
                float mx0 = m0, mx1 = m1;
#pragma unroll
                for (int t = 0; t < 8; t++) {
                    mx0 = fmaxf(mx0, fmaxf(sc[t][0], sc[t][1]));
                    mx1 = fmaxf(mx1, fmaxf(sc[t][2], sc[t][3]));
                }
                mx0 = fmaxf(mx0, __shfl_xor_sync(0xffffffffu, mx0, 1));
                mx0 = fmaxf(mx0, __shfl_xor_sync(0xffffffffu, mx0, 2));
                mx1 = fmaxf(mx1, __shfl_xor_sync(0xffffffffu, mx1, 1));
                mx1 = fmaxf(mx1, __shfl_xor_sync(0xffffffffu, mx1, 2));

                const float a0 = __expf(m0 - mx0);
                const float a1 = __expf(m1 - mx1);
                float s0 = 0.f, s1 = 0.f;
#pragma unroll
                for (int t = 0; t < 8; t++) {
                    float p;
                    p = rtf(__expf(sc[t][0] - mx0)); sc[t][0] = p; s0 += p;
                    p = rtf(__expf(sc[t][1] - mx0)); sc[t][1] = p; s0 += p;
                    p = rtf(__expf(sc[t][2] - mx1)); sc[t][2] = p; s1 += p;
                    p = rtf(__expf(sc[t][3] - mx1)); sc[t][3] = p; s1 += p;
                }
                s0 += __shfl_xor_sync(0xffffffffu, s0, 1);
                s0 += __shfl_xor_sync(0xffffffffu, s0, 2);
                s1 += __shfl_xor_sync(0xffffffffu, s1, 1);
                s1 += __shfl_xor_sync(0xffffffffu, s1, 2);
                l0 = l0 * a0 + s0;  l1 = l1 * a1 + s1;
                m0 = mx0;           m1 = mx1;
#pragma unroll
                for (int t = 0; t < 8; t++) {
                    oc[t][0] *= a0; oc[t][1] *= a0;
                    oc[t][2] *= a1; oc[t][3] *= a1;
                }
            }

            // ---- O += P @ V : P acc-layout -> A-frag via quad shfl ----
            const int srcA = (lane & ~3) | (q >> 1);
            const int srcB = srcA + 2;
            const bool odd = (q & 1);
#pragma unroll
            for (int j = 0; j < 8; j++) {
                float v00 = __shfl_sync(0xffffffffu, sc[j][0], srcA);
                float v01 = __shfl_sync(0xffffffffu, sc[j][1], srcA);
                float v20 = __shfl_sync(0xffffffffu, sc[j][2], srcA);
                float v21 = __shfl_sync(0xffffffffu, sc[j][3], srcA);
                float w00 = __shfl_sync(0xffffffffu, sc[j][0], srcB);
                float w01 = __shfl_sync(0xffffffffu, sc[j][1], srcB);
                float w20 = __shfl_sync(0xffffffffu, sc[j][2], srcB);
                float w21 = __shfl_sync(0xffffffffu, sc[j][3], srcB);
                uint32_t pa[4];
                pa[0] = __float_as_uint(odd ? v01 : v00);
                pa[1] = __float_as_uint(odd ? v21 : v20);
                pa[2] = __float_as_uint(odd ? w01 : w00);
                pa[3] = __float_as_uint(odd ? w21 : w20);
#pragma unroll
                for (int t = 0; t < 8; t++) {
                    uint32_t b0 = __float_as_uint(Vs[(j * 8 + q    ) * ATS + t * 8 + g]);
                    uint32_t b1 = __float_as_uint(Vs[(j * 8 + q + 4) * ATS + t * 8 + g]);
                    mma8(oc[t], pa, b0, b1);
                }
            }
        }

        CP_WAIT0();            // next K/V tile landed
        __syncthreads();       // buffer rotation
    }

    // ---- epilogue: normalize, round, write ctx ----
    const float inv0 = 1.f / l0, inv1 = 1.f / l1;
    const int b = bh / HH, h = bh % HH;
    float* base = &g_ctx[((size_t)b * SS + row0g) * DD + h * HD];
#pragma unroll
    for (int t = 0; t < 8; t++) {
        float2 w0, w1;
        w0.x = rtf(oc[t][0] * inv0); w0.y = rtf(oc[t][1] * inv0);
        w1.x = rtf(oc[t][2] * inv1); w1.y = rtf(oc[t][3] * inv1);
        *(float2*)&base[t * 8 + 2 * q] = w0;
        *(float2*)&base[(size_t)8 * DD + t * 8 + 2 * q] = w1;
    }
}

// ---------------------------------------------------------------------------
extern "C" void kernel_launch(void* const* d_in, const int* in_sizes, int n_in,
                              void* d_out, int out_size)
{
    const float* x  = (const float*)d_in[0];
    const float* Wq = (const float*)d_in[1];
    const float* bq = (const float*)d_in[2];
    const float* Wk = (const float*)d_in[3];
    const float* bk = (const float*)d_in[4];
    const float* Wv = (const float*)d_in[5];
    const float* bv = (const float*)d_in[6];
    const float* Wo = (const float*)d_in[7];
    const float* bo = (const float*)d_in[8];
    float* out = (float*)d_out;

    cudaFuncSetAttribute(gemm_wmma<true>,  cudaFuncAttributeMaxDynamicSharedMemorySize, SMEM_BYTES);
    cudaFuncSetAttribute(gemm_wmma<false>, cudaFuncAttributeMaxDynamicSharedMemorySize, SMEM_BYTES);
    cudaFuncSetAttribute(attn_mma, cudaFuncAttributeMaxDynamicSharedMemorySize, ATT_SMEM_BYTES);

    conv_tf32<<<dim3(512, 1, 5), 256>>>(x, Wq, Wk, Wv, Wo);

    dim3 gqkv(DD / 128, NROWS / 128, 3);
    gemm_wmma<true><<<gqkv, 256, SMEM_BYTES>>>(bq, bk, bv, nullptr);

    dim3 gattn(SS / 128, BB * HH);            // (16, 32)
    attn_mma<<<gattn, 256, ATT_SMEM_BYTES>>>();

    dim3 gout(DD / 128, NROWS / 128);
    gemm_wmma<false><<<gout, 256, SMEM_BYTES>>>(bo, nullptr, nullptr, out);
}